// round 2
// baseline (speedup 1.0000x reference)
#include <cuda_runtime.h>

#define ROWS_TOTAL 16384
#define DMODEL 256

// Scratch (static device arrays — no allocation in kernel_launch).
__device__ __align__(16) float g_Qh[ROWS_TOTAL * DMODEL];
__device__ __align__(16) float g_Kh[ROWS_TOTAL * DMODEL];
__device__ __align__(16) float g_Vh[ROWS_TOTAL * DMODEL];
__device__ __align__(16) float g_AV[ROWS_TOTAL * DMODEL];

// ---------------------------------------------------------------------------
// C[R,256] = A[R,256] @ W[256,256] + bias   (all row-major fp32)
// 128x128 block tile, BK=16, 256 threads, 8x8 per thread.
// ---------------------------------------------------------------------------
__global__ __launch_bounds__(256, 2) void gemm_bias_kernel(
    const float* __restrict__ A, const float* __restrict__ W,
    const float* __restrict__ bias, float* __restrict__ C)
{
    __shared__ float As[16][128];   // transposed A tile: As[k][m]
    __shared__ float Bs[16][128];   // Bs[k][n]

    const int tid = threadIdx.x;
    const int tx  = tid & 15;       // 0..15 -> n
    const int ty  = tid >> 4;       // 0..15 -> m
    const int m0  = blockIdx.y * 128;
    const int n0  = blockIdx.x * 128;

    float acc[8][8];
    #pragma unroll
    for (int i = 0; i < 8; i++)
        #pragma unroll
        for (int j = 0; j < 8; j++) acc[i][j] = 0.f;

    for (int k0 = 0; k0 < DMODEL; k0 += 16) {
        // A tile: 128 rows x 16 cols = 512 float4, 2 per thread.
        #pragma unroll
        for (int l = 0; l < 2; l++) {
            int idx = tid + l * 256;      // 0..511
            int row = idx >> 2;
            int c4  = idx & 3;
            float4 v = *(const float4*)&A[(size_t)(m0 + row) * DMODEL + k0 + c4 * 4];
            As[c4 * 4 + 0][row] = v.x;
            As[c4 * 4 + 1][row] = v.y;
            As[c4 * 4 + 2][row] = v.z;
            As[c4 * 4 + 3][row] = v.w;
        }
        // W tile: 16 rows x 128 cols = 512 float4, 2 per thread.
        #pragma unroll
        for (int l = 0; l < 2; l++) {
            int idx = tid + l * 256;
            int row = idx >> 5;           // 0..15
            int c4  = idx & 31;
            *(float4*)&Bs[row][c4 * 4] =
                *(const float4*)&W[(size_t)(k0 + row) * DMODEL + n0 + c4 * 4];
        }
        __syncthreads();

        #pragma unroll
        for (int kk = 0; kk < 16; kk++) {
            float fa[8], fb[8];
            #pragma unroll
            for (int i = 0; i < 4; i++) {
                fa[i]     = As[kk][ty * 8 + i];
                fa[i + 4] = As[kk][ty * 8 + 4 + i];
                fb[i]     = Bs[kk][tx * 8 + i];
                fb[i + 4] = Bs[kk][tx * 8 + 4 + i];
            }
            #pragma unroll
            for (int i = 0; i < 8; i++)
                #pragma unroll
                for (int j = 0; j < 8; j++)
                    acc[i][j] = fmaf(fa[i], fb[j], acc[i][j]);
        }
        __syncthreads();
    }

    // Epilogue: bias + float4 stores.
    #pragma unroll
    for (int i = 0; i < 8; i++) {
        int r = m0 + ty * 8 + i;
        #pragma unroll
        for (int j = 0; j < 8; j += 4) {
            int c = n0 + tx * 8 + j;
            float4 v;
            v.x = acc[i][j + 0] + bias[c + 0];
            v.y = acc[i][j + 1] + bias[c + 1];
            v.z = acc[i][j + 2] + bias[c + 2];
            v.w = acc[i][j + 3] + bias[c + 3];
            *(float4*)&C[(size_t)r * DMODEL + c] = v;
        }
    }
}

// ---------------------------------------------------------------------------
// kNN attention: one block per query (16384 blocks), 256 threads = 8 warps,
// warp h handles head h. k=32 neighbours, head dim = 32.
// ---------------------------------------------------------------------------
__global__ __launch_bounds__(256) void knn_attn_kernel(const int* __restrict__ nb)
{
    __shared__ float Ks[32 * 257];   // 32 neighbour rows, stride 257 (bank-safe)
    __shared__ float qs[256];
    __shared__ int   s_row[32];

    const int tid = threadIdx.x;
    const int q   = blockIdx.x;          // flattened (b, n)
    const int b   = q >> 13;             // N = 8192

    if (tid < 32) s_row[tid] = (b << 13) + nb[(size_t)q * 32 + tid];
    qs[tid] = g_Qh[(size_t)q * DMODEL + tid];
    __syncthreads();

    // Stage gathered K rows: thread -> (neighbour j = tid&31, 32-float part).
    // STS pattern: lane j varies within warp, same part -> bank (j*257+c)%32
    // = (j+c)%32 -> conflict-free.
    {
        const int j    = tid & 31;
        const int part = tid >> 5;       // 0..7
        const int row  = s_row[j];
        const float4* src = (const float4*)&g_Kh[(size_t)row * DMODEL + part * 32];
        float* dst = &Ks[j * 257 + part * 32];
        #pragma unroll
        for (int i = 0; i < 8; i++) {
            float4 v = src[i];
            dst[i * 4 + 0] = v.x;
            dst[i * 4 + 1] = v.y;
            dst[i * 4 + 2] = v.z;
            dst[i * 4 + 3] = v.w;
        }
    }
    __syncthreads();

    const int h    = tid >> 5;
    const int lane = tid & 31;

    // E[lane] = dot(Qh[head h], Kn[lane, head h]) * 1/sqrt(256)
    const float* krow = &Ks[lane * 257 + h * 32];
    const float* qh   = &qs[h * 32];
    float e = 0.f;
    #pragma unroll
    for (int d = 0; d < 32; d++) e = fmaf(qh[d], krow[d], e);
    e *= 0.0625f;

    // Softmax over 32 lanes.
    float m = e;
    #pragma unroll
    for (int o = 16; o > 0; o >>= 1)
        m = fmaxf(m, __shfl_xor_sync(0xffffffffu, m, o));
    float p = __expf(e - m);
    float s = p;
    #pragma unroll
    for (int o = 16; o > 0; o >>= 1)
        s += __shfl_xor_sync(0xffffffffu, s, o);
    const float a = p / s;

    // AV[h*32 + lane] = sum_j a_j * Vh[row_j][h*32 + lane]  (coalesced 128B/ldg)
    float acc = 0.f;
    #pragma unroll
    for (int j = 0; j < 32; j++) {
        float aj = __shfl_sync(0xffffffffu, a, j);
        int row  = s_row[j];
        acc = fmaf(aj, g_Vh[(size_t)row * DMODEL + h * 32 + lane], acc);
    }
    g_AV[(size_t)q * DMODEL + h * 32 + lane] = acc;
}

// ---------------------------------------------------------------------------
extern "C" void kernel_launch(void* const* d_in, const int* in_sizes, int n_in,
                              void* d_out, int out_size)
{
    const float* Q  = (const float*)d_in[0];
    const float* K  = (const float*)d_in[1];
    const int*   nb = (const int*)d_in[2];
    const float* Wq = (const float*)d_in[3];
    const float* bq = (const float*)d_in[4];
    const float* Wk = (const float*)d_in[5];
    const float* bk = (const float*)d_in[6];
    const float* Wv = (const float*)d_in[7];
    const float* bv = (const float*)d_in[8];
    const float* Wo = (const float*)d_in[9];
    const float* bo = (const float*)d_in[10];
    float* out = (float*)d_out;

    float *Qh, *Kh, *Vh, *AV;
    cudaGetSymbolAddress((void**)&Qh, g_Qh);
    cudaGetSymbolAddress((void**)&Kh, g_Kh);
    cudaGetSymbolAddress((void**)&Vh, g_Vh);
    cudaGetSymbolAddress((void**)&AV, g_AV);

    dim3 ggrid(2, 128);   // 256 cols / 128, 16384 rows / 128
    gemm_bias_kernel<<<ggrid, 256>>>(K, Wk, bk, Kh);
    gemm_bias_kernel<<<ggrid, 256>>>(K, Wv, bv, Vh);
    gemm_bias_kernel<<<ggrid, 256>>>(Q, Wq, bq, Qh);
    knn_attn_kernel<<<16384, 256>>>(nb);
    gemm_bias_kernel<<<ggrid, 256>>>(AV, Wo, bo, out);
}

// round 3
// speedup vs baseline: 1.3778x; 1.3778x over previous
#include <cuda_runtime.h>

#define ROWS_TOTAL 16384
#define DMODEL 256

// Scratch (static device arrays — no allocation in kernel_launch).
__device__ __align__(16) float g_Qh[ROWS_TOTAL * DMODEL];
__device__ __align__(16) float g_Kh[ROWS_TOTAL * DMODEL];
__device__ __align__(16) float g_Vh[ROWS_TOTAL * DMODEL];
__device__ __align__(16) float g_AV[ROWS_TOTAL * DMODEL];

// ---------------------------------------------------------------------------
// C[R,256] = A[R,256] @ W[256,256] + bias   (all row-major fp32)
// 128x128 block tile, BK=16, 256 threads, 8x8 per thread.
// Already at the fp32-FFMA roofline — unchanged.
// ---------------------------------------------------------------------------
__global__ __launch_bounds__(256, 2) void gemm_bias_kernel(
    const float* __restrict__ A, const float* __restrict__ W,
    const float* __restrict__ bias, float* __restrict__ C)
{
    __shared__ float As[16][128];   // transposed A tile: As[k][m]
    __shared__ float Bs[16][128];   // Bs[k][n]

    const int tid = threadIdx.x;
    const int tx  = tid & 15;       // 0..15 -> n
    const int ty  = tid >> 4;       // 0..15 -> m
    const int m0  = blockIdx.y * 128;
    const int n0  = blockIdx.x * 128;

    float acc[8][8];
    #pragma unroll
    for (int i = 0; i < 8; i++)
        #pragma unroll
        for (int j = 0; j < 8; j++) acc[i][j] = 0.f;

    for (int k0 = 0; k0 < DMODEL; k0 += 16) {
        #pragma unroll
        for (int l = 0; l < 2; l++) {
            int idx = tid + l * 256;      // 0..511
            int row = idx >> 2;
            int c4  = idx & 3;
            float4 v = *(const float4*)&A[(size_t)(m0 + row) * DMODEL + k0 + c4 * 4];
            As[c4 * 4 + 0][row] = v.x;
            As[c4 * 4 + 1][row] = v.y;
            As[c4 * 4 + 2][row] = v.z;
            As[c4 * 4 + 3][row] = v.w;
        }
        #pragma unroll
        for (int l = 0; l < 2; l++) {
            int idx = tid + l * 256;
            int row = idx >> 5;           // 0..15
            int c4  = idx & 31;
            *(float4*)&Bs[row][c4 * 4] =
                *(const float4*)&W[(size_t)(k0 + row) * DMODEL + n0 + c4 * 4];
        }
        __syncthreads();

        #pragma unroll
        for (int kk = 0; kk < 16; kk++) {
            float fa[8], fb[8];
            #pragma unroll
            for (int i = 0; i < 4; i++) {
                fa[i]     = As[kk][ty * 8 + i];
                fa[i + 4] = As[kk][ty * 8 + 4 + i];
                fb[i]     = Bs[kk][tx * 8 + i];
                fb[i + 4] = Bs[kk][tx * 8 + 4 + i];
            }
            #pragma unroll
            for (int i = 0; i < 8; i++)
                #pragma unroll
                for (int j = 0; j < 8; j++)
                    acc[i][j] = fmaf(fa[i], fb[j], acc[i][j]);
        }
        __syncthreads();
    }

    #pragma unroll
    for (int i = 0; i < 8; i++) {
        int r = m0 + ty * 8 + i;
        #pragma unroll
        for (int j = 0; j < 8; j += 4) {
            int c = n0 + tx * 8 + j;
            float4 v;
            v.x = acc[i][j + 0] + bias[c + 0];
            v.y = acc[i][j + 1] + bias[c + 1];
            v.z = acc[i][j + 2] + bias[c + 2];
            v.w = acc[i][j + 3] + bias[c + 3];
            *(float4*)&C[(size_t)r * DMODEL + c] = v;
        }
    }
}

// ---------------------------------------------------------------------------
// kNN attention: one block per query (16384 blocks), 256 threads = 8 warps.
//
// Phase 1 (score): warp w owns neighbours 4w..4w+3; lane d owns dims
//   [8d, 8d+8). K-row loads are fully coalesced (1KB/row). 8-wide per-lane
//   dot, then quad reduction (2 shfls) gives all 8 head scores; written to
//   a tiny E[32][9] transpose buffer (stride 9: gcd(9,32)=1, bank-safe).
// Phase 2 (softmax): warp h reads E[lane][h], shfl softmax over 32 lanes.
// Phase 3 (AV): warp h, lane d: coalesced 128B V-row slices, shfl-broadcast
//   of attention weights.
// No 32KB K staging -> smem ~1.4KB, occupancy-limited only by warps.
// ---------------------------------------------------------------------------
__global__ __launch_bounds__(256) void knn_attn_kernel(const int* __restrict__ nb)
{
    __shared__ float Es[32][9];     // [neighbour][head], pad to 9
    __shared__ int   s_row[32];

    const int tid  = threadIdx.x;
    const int q    = blockIdx.x;         // flattened (b, n)
    const int b    = q >> 13;            // N = 8192
    const int w    = tid >> 5;
    const int lane = tid & 31;

    if (tid < 32) s_row[tid] = (b << 13) + nb[(size_t)q * 32 + tid];
    __syncthreads();

    // ---- Phase 1: scores ----
    {
        const float4* qp = (const float4*)&g_Qh[(size_t)q * DMODEL + lane * 8];
        float4 q0 = qp[0];
        float4 q1 = qp[1];

        #pragma unroll
        for (int i = 0; i < 4; i++) {
            const int j   = w * 4 + i;
            const int row = s_row[j];
            const float4* kp = (const float4*)&g_Kh[(size_t)row * DMODEL + lane * 8];
            float4 k0 = kp[0];
            float4 k1 = kp[1];
            float p = q0.x * k0.x;
            p = fmaf(q0.y, k0.y, p);
            p = fmaf(q0.z, k0.z, p);
            p = fmaf(q0.w, k0.w, p);
            p = fmaf(q1.x, k1.x, p);
            p = fmaf(q1.y, k1.y, p);
            p = fmaf(q1.z, k1.z, p);
            p = fmaf(q1.w, k1.w, p);
            // reduce across the 4 lanes of this head's quad
            p += __shfl_xor_sync(0xffffffffu, p, 1);
            p += __shfl_xor_sync(0xffffffffu, p, 2);
            if ((lane & 3) == 0) Es[j][lane >> 2] = p * 0.0625f;  // 1/sqrt(256)
        }
    }
    __syncthreads();

    // ---- Phase 2: softmax (warp h over its 32 neighbour scores) ----
    const int h = w;
    float e = Es[lane][h];
    float m = e;
    #pragma unroll
    for (int o = 16; o > 0; o >>= 1)
        m = fmaxf(m, __shfl_xor_sync(0xffffffffu, m, o));
    float p = __expf(e - m);
    float s = p;
    #pragma unroll
    for (int o = 16; o > 0; o >>= 1)
        s += __shfl_xor_sync(0xffffffffu, s, o);
    const float a = p / s;

    // ---- Phase 3: AV (coalesced 128B per (warp, neighbour)) ----
    float acc0 = 0.f, acc1 = 0.f, acc2 = 0.f, acc3 = 0.f;
    const size_t off = (size_t)h * 32 + lane;
    #pragma unroll
    for (int j = 0; j < 32; j += 4) {
        float v0 = g_Vh[(size_t)s_row[j + 0] * DMODEL + off];
        float v1 = g_Vh[(size_t)s_row[j + 1] * DMODEL + off];
        float v2 = g_Vh[(size_t)s_row[j + 2] * DMODEL + off];
        float v3 = g_Vh[(size_t)s_row[j + 3] * DMODEL + off];
        acc0 = fmaf(__shfl_sync(0xffffffffu, a, j + 0), v0, acc0);
        acc1 = fmaf(__shfl_sync(0xffffffffu, a, j + 1), v1, acc1);
        acc2 = fmaf(__shfl_sync(0xffffffffu, a, j + 2), v2, acc2);
        acc3 = fmaf(__shfl_sync(0xffffffffu, a, j + 3), v3, acc3);
    }
    g_AV[(size_t)q * DMODEL + off] = (acc0 + acc1) + (acc2 + acc3);
}

// ---------------------------------------------------------------------------
extern "C" void kernel_launch(void* const* d_in, const int* in_sizes, int n_in,
                              void* d_out, int out_size)
{
    const float* Q  = (const float*)d_in[0];
    const float* K  = (const float*)d_in[1];
    const int*   nb = (const int*)d_in[2];
    const float* Wq = (const float*)d_in[3];
    const float* bq = (const float*)d_in[4];
    const float* Wk = (const float*)d_in[5];
    const float* bk = (const float*)d_in[6];
    const float* Wv = (const float*)d_in[7];
    const float* bv = (const float*)d_in[8];
    const float* Wo = (const float*)d_in[9];
    const float* bo = (const float*)d_in[10];
    float* out = (float*)d_out;

    float *Qh, *Kh, *Vh, *AV;
    cudaGetSymbolAddress((void**)&Qh, g_Qh);
    cudaGetSymbolAddress((void**)&Kh, g_Kh);
    cudaGetSymbolAddress((void**)&Vh, g_Vh);
    cudaGetSymbolAddress((void**)&AV, g_AV);

    dim3 ggrid(2, 128);   // 256 cols / 128, 16384 rows / 128
    gemm_bias_kernel<<<ggrid, 256>>>(K, Wk, bk, Kh);
    gemm_bias_kernel<<<ggrid, 256>>>(K, Wv, bv, Vh);
    gemm_bias_kernel<<<ggrid, 256>>>(Q, Wq, bq, Qh);
    knn_attn_kernel<<<16384, 256>>>(nb);
    gemm_bias_kernel<<<ggrid, 256>>>(AV, Wo, bo, out);
}

// round 7
// speedup vs baseline: 2.0882x; 1.5157x over previous
#include <cuda_runtime.h>
#include <cuda_bf16.h>
#include <cstdint>

#define ROWS_TOTAL 16384
#define DMODEL 256

// ---------------------------------------------------------------------------
// Scratch (static device arrays — no allocation in kernel_launch).
// ---------------------------------------------------------------------------
__device__ __align__(16) float g_Qh[ROWS_TOTAL * DMODEL];
__device__ __align__(16) float g_Kh[ROWS_TOTAL * DMODEL];
__device__ __align__(16) float g_Vh[ROWS_TOTAL * DMODEL];
__device__ __align__(16) float g_AV[ROWS_TOTAL * DMODEL];
// Transposed + bf16-split weights: [mat][N=256][K=256]
__device__ __align__(16) __nv_bfloat16 g_Wth[4 * 65536];
__device__ __align__(16) __nv_bfloat16 g_Wtl[4 * 65536];

// ---------------------------------------------------------------------------
// Warp-level tensor-core primitives (base-target: ldmatrix sm_75+, bf16 mma sm_80+)
// ---------------------------------------------------------------------------
__device__ __forceinline__ uint32_t smem_to_u32(const void* smem_ptr) {
    uint32_t addr;
    asm("{ .reg .u64 tmp; cvta.to.shared.u64 tmp, %1; cvt.u32.u64 %0, tmp; }"
        : "=r"(addr) : "l"(smem_ptr));
    return addr;
}

#define LDMATRIX_X4(r0, r1, r2, r3, addr) \
    asm volatile("ldmatrix.sync.aligned.m8n8.x4.shared.b16 {%0,%1,%2,%3}, [%4];" \
                 : "=r"(r0), "=r"(r1), "=r"(r2), "=r"(r3) : "r"(addr))

#define LDMATRIX_X2(r0, r1, addr) \
    asm volatile("ldmatrix.sync.aligned.m8n8.x2.shared.b16 {%0,%1}, [%2];" \
                 : "=r"(r0), "=r"(r1) : "r"(addr))

#define MMA_BF16(d, a, b) \
    asm volatile("mma.sync.aligned.m16n8k16.row.col.f32.bf16.bf16.f32 " \
                 "{%0,%1,%2,%3}, {%4,%5,%6,%7}, {%8,%9}, {%0,%1,%2,%3};" \
                 : "+f"((d)[0]), "+f"((d)[1]), "+f"((d)[2]), "+f"((d)[3]) \
                 : "r"((a)[0]), "r"((a)[1]), "r"((a)[2]), "r"((a)[3]), \
                   "r"((b)[0]), "r"((b)[1]))

// ---------------------------------------------------------------------------
// Weight prep: Wt_hi/lo[mat][n][k] = bf16 split of W[k][n]
// ---------------------------------------------------------------------------
__global__ void prep_w_kernel(const float* __restrict__ Wq, const float* __restrict__ Wk,
                              const float* __restrict__ Wv, const float* __restrict__ Wo)
{
    const int mat = blockIdx.y;
    const float* W = (mat == 0) ? Wq : (mat == 1) ? Wk : (mat == 2) ? Wv : Wo;
    const int n = blockIdx.x;
    const int k = threadIdx.x;
    float f = W[k * 256 + n];
    __nv_bfloat16 h = __float2bfloat16(f);
    float l = f - __bfloat162float(h);
    g_Wth[mat * 65536 + n * 256 + k] = h;
    g_Wtl[mat * 65536 + n * 256 + k] = __float2bfloat16(l);
}

// ---------------------------------------------------------------------------
// HMMA bf16 split-3 GEMM: C[16384,256] = A[16384,256] @ W[256,256] + bias
//   W passed pre-transposed & split: Wth/Wtl[n][k]  (col-major B for row.col mma)
//   BM=128, BN=128, BK=32, 256 threads (8 warps: 4m x 2n; warp tile 32x64).
//   Split-3: Ah*Wh + Ah*Wl + Al*Wh, fp32 accumulate -> residual ~2^-16.
//   Smem rows padded to 80B: ldmatrix lane addrs r*80 + 16c hit all 32 banks.
// ---------------------------------------------------------------------------
#define AH_OFF 0
#define AL_OFF 10240
#define WH_OFF 20480
#define WL_OFF 30720

__global__ void __launch_bounds__(256) gemm_tc_kernel(
    const float* __restrict__ A,
    const __nv_bfloat16* __restrict__ Wth,
    const __nv_bfloat16* __restrict__ Wtl,
    const float* __restrict__ bias,
    float* __restrict__ C)
{
    __shared__ __align__(16) char smem[40960];
    const uint32_t sb = smem_to_u32(smem);

    const int tid    = threadIdx.x;
    const int lane   = tid & 31;
    const int wid    = tid >> 5;
    const int warp_m = wid & 3;      // 4 warps along M
    const int warp_n = wid >> 2;     // 2 warps along N
    const int m0     = blockIdx.y * 128;
    const int n0     = blockIdx.x * 128;

    float acc[2][8][4];
    #pragma unroll
    for (int mt = 0; mt < 2; mt++)
        #pragma unroll
        for (int nt = 0; nt < 8; nt++)
            #pragma unroll
            for (int i = 0; i < 4; i++) acc[mt][nt][i] = 0.f;

    // staging indices (each thread: one row, 16 k-values = 64B)
    const int st_r    = tid >> 1;        // 0..127
    const int st_koff = (tid & 1) * 16;  // 0 or 16

    for (int c = 0; c < 8; c++) {
        const int k0 = c * 32;

        // ---- stage A chunk (128 x 32) as bf16 hi/lo ----
        {
            const float* ap = &A[(size_t)(m0 + st_r) * DMODEL + k0 + st_koff];
            float4 f0 = *(const float4*)(ap + 0);
            float4 f1 = *(const float4*)(ap + 4);
            float4 f2 = *(const float4*)(ap + 8);
            float4 f3 = *(const float4*)(ap + 12);
            float v[16];
            v[0]=f0.x; v[1]=f0.y; v[2]=f0.z; v[3]=f0.w;
            v[4]=f1.x; v[5]=f1.y; v[6]=f1.z; v[7]=f1.w;
            v[8]=f2.x; v[9]=f2.y; v[10]=f2.z; v[11]=f2.w;
            v[12]=f3.x; v[13]=f3.y; v[14]=f3.z; v[15]=f3.w;
            uint32_t hi[8], lo[8];
            #pragma unroll
            for (int i = 0; i < 8; i++) {
                float x = v[2*i], y = v[2*i+1];
                __nv_bfloat16 hx = __float2bfloat16(x);
                __nv_bfloat16 hy = __float2bfloat16(y);
                __nv_bfloat162 hp; hp.x = hx; hp.y = hy;
                hi[i] = *reinterpret_cast<uint32_t*>(&hp);
                __nv_bfloat162 lp;
                lp.x = __float2bfloat16(x - __bfloat162float(hx));
                lp.y = __float2bfloat16(y - __bfloat162float(hy));
                lo[i] = *reinterpret_cast<uint32_t*>(&lp);
            }
            char* dh = smem + AH_OFF + st_r * 80 + st_koff * 2;
            char* dl = smem + AL_OFF + st_r * 80 + st_koff * 2;
            uint4 u;
            u.x=hi[0]; u.y=hi[1]; u.z=hi[2]; u.w=hi[3]; *(uint4*)(dh)      = u;
            u.x=hi[4]; u.y=hi[5]; u.z=hi[6]; u.w=hi[7]; *(uint4*)(dh + 16) = u;
            u.x=lo[0]; u.y=lo[1]; u.z=lo[2]; u.w=lo[3]; *(uint4*)(dl)      = u;
            u.x=lo[4]; u.y=lo[5]; u.z=lo[6]; u.w=lo[7]; *(uint4*)(dl + 16) = u;
        }

        // ---- stage W chunk (128 n-rows x 32 k) bf16 hi/lo ----
        {
            const __nv_bfloat16* wh = &Wth[(size_t)(n0 + st_r) * DMODEL + k0 + st_koff];
            const __nv_bfloat16* wl = &Wtl[(size_t)(n0 + st_r) * DMODEL + k0 + st_koff];
            uint4 h0 = *(const uint4*)(wh);
            uint4 h1 = *(const uint4*)(wh + 8);
            uint4 l0 = *(const uint4*)(wl);
            uint4 l1 = *(const uint4*)(wl + 8);
            char* dh = smem + WH_OFF + st_r * 80 + st_koff * 2;
            char* dl = smem + WL_OFF + st_r * 80 + st_koff * 2;
            *(uint4*)(dh)      = h0;
            *(uint4*)(dh + 16) = h1;
            *(uint4*)(dl)      = l0;
            *(uint4*)(dl + 16) = l1;
        }

        __syncthreads();

        // ---- compute: 2 k-steps of 16 ----
        #pragma unroll
        for (int ks = 0; ks < 2; ks++) {
            // A fragments: ldmatrix.x4 — matrices (m0k0, m8k0, m0k8, m8k8)
            const int aidx  = lane >> 3;                       // 0..3
            const int a_m   = (aidx & 1) * 8 + (lane & 7);
            const int a_k   = (aidx >> 1) * 8;
            uint32_t ah[2][4], al[2][4];
            #pragma unroll
            for (int mt = 0; mt < 2; mt++) {
                const uint32_t row = (uint32_t)(warp_m * 32 + mt * 16 + a_m);
                const uint32_t col = (uint32_t)(ks * 16 + a_k) * 2u;
                LDMATRIX_X4(ah[mt][0], ah[mt][1], ah[mt][2], ah[mt][3],
                            sb + AH_OFF + row * 80u + col);
                LDMATRIX_X4(al[mt][0], al[mt][1], al[mt][2], al[mt][3],
                            sb + AL_OFF + row * 80u + col);
            }
            // B fragments: ldmatrix.x2 — matrices (n rows k0-7, k8-15)
            const int l2   = lane & 15;
            const int b_n  = l2 & 7;
            const int b_k  = (l2 >> 3) * 8;
            uint32_t bh[8][2], bl[8][2];
            #pragma unroll
            for (int nt = 0; nt < 8; nt++) {
                const uint32_t row = (uint32_t)(warp_n * 64 + nt * 8 + b_n);
                const uint32_t col = (uint32_t)(ks * 16 + b_k) * 2u;
                LDMATRIX_X2(bh[nt][0], bh[nt][1], sb + WH_OFF + row * 80u + col);
                LDMATRIX_X2(bl[nt][0], bl[nt][1], sb + WL_OFF + row * 80u + col);
            }
            #pragma unroll
            for (int mt = 0; mt < 2; mt++) {
                #pragma unroll
                for (int nt = 0; nt < 8; nt++) {
                    MMA_BF16(acc[mt][nt], ah[mt], bh[nt]);
                    MMA_BF16(acc[mt][nt], ah[mt], bl[nt]);
                    MMA_BF16(acc[mt][nt], al[mt], bh[nt]);
                }
            }
        }
        __syncthreads();
    }

    // ---- epilogue: bias + store (float2 per acc pair) ----
    const int gr = lane >> 2;
    const int gc = (lane & 3) * 2;
    #pragma unroll
    for (int mt = 0; mt < 2; mt++) {
        const int mrow = m0 + warp_m * 32 + mt * 16 + gr;
        #pragma unroll
        for (int nt = 0; nt < 8; nt++) {
            const int ncol = n0 + warp_n * 64 + nt * 8 + gc;
            const float2 bv = *(const float2*)&bias[ncol];
            float2 o;
            o.x = acc[mt][nt][0] + bv.x;
            o.y = acc[mt][nt][1] + bv.y;
            *(float2*)&C[(size_t)mrow * DMODEL + ncol] = o;
            o.x = acc[mt][nt][2] + bv.x;
            o.y = acc[mt][nt][3] + bv.y;
            *(float2*)&C[(size_t)(mrow + 8) * DMODEL + ncol] = o;
        }
    }
}

// ---------------------------------------------------------------------------
// kNN attention (unchanged from round 3): one block per query, 8 warps.
// ---------------------------------------------------------------------------
__global__ void __launch_bounds__(256) knn_attn_kernel(const int* __restrict__ nb)
{
    __shared__ float Es[32][9];
    __shared__ int   s_row[32];

    const int tid  = threadIdx.x;
    const int q    = blockIdx.x;
    const int b    = q >> 13;
    const int w    = tid >> 5;
    const int lane = tid & 31;

    if (tid < 32) s_row[tid] = (b << 13) + nb[(size_t)q * 32 + tid];
    __syncthreads();

    {
        const float4* qp = (const float4*)&g_Qh[(size_t)q * DMODEL + lane * 8];
        float4 q0 = qp[0];
        float4 q1 = qp[1];

        #pragma unroll
        for (int i = 0; i < 4; i++) {
            const int j   = w * 4 + i;
            const int row = s_row[j];
            const float4* kp = (const float4*)&g_Kh[(size_t)row * DMODEL + lane * 8];
            float4 k0 = kp[0];
            float4 k1 = kp[1];
            float p = q0.x * k0.x;
            p = fmaf(q0.y, k0.y, p);
            p = fmaf(q0.z, k0.z, p);
            p = fmaf(q0.w, k0.w, p);
            p = fmaf(q1.x, k1.x, p);
            p = fmaf(q1.y, k1.y, p);
            p = fmaf(q1.z, k1.z, p);
            p = fmaf(q1.w, k1.w, p);
            p += __shfl_xor_sync(0xffffffffu, p, 1);
            p += __shfl_xor_sync(0xffffffffu, p, 2);
            if ((lane & 3) == 0) Es[j][lane >> 2] = p * 0.0625f;
        }
    }
    __syncthreads();

    const int h = w;
    float e = Es[lane][h];
    float m = e;
    #pragma unroll
    for (int o = 16; o > 0; o >>= 1)
        m = fmaxf(m, __shfl_xor_sync(0xffffffffu, m, o));
    float p = __expf(e - m);
    float s = p;
    #pragma unroll
    for (int o = 16; o > 0; o >>= 1)
        s += __shfl_xor_sync(0xffffffffu, s, o);
    const float a = p / s;

    float acc0 = 0.f, acc1 = 0.f, acc2 = 0.f, acc3 = 0.f;
    const size_t off = (size_t)h * 32 + lane;
    #pragma unroll
    for (int j = 0; j < 32; j += 4) {
        float v0 = g_Vh[(size_t)s_row[j + 0] * DMODEL + off];
        float v1 = g_Vh[(size_t)s_row[j + 1] * DMODEL + off];
        float v2 = g_Vh[(size_t)s_row[j + 2] * DMODEL + off];
        float v3 = g_Vh[(size_t)s_row[j + 3] * DMODEL + off];
        acc0 = fmaf(__shfl_sync(0xffffffffu, a, j + 0), v0, acc0);
        acc1 = fmaf(__shfl_sync(0xffffffffu, a, j + 1), v1, acc1);
        acc2 = fmaf(__shfl_sync(0xffffffffu, a, j + 2), v2, acc2);
        acc3 = fmaf(__shfl_sync(0xffffffffu, a, j + 3), v3, acc3);
    }
    g_AV[(size_t)q * DMODEL + off] = (acc0 + acc1) + (acc2 + acc3);
}

// ---------------------------------------------------------------------------
extern "C" void kernel_launch(void* const* d_in, const int* in_sizes, int n_in,
                              void* d_out, int out_size)
{
    const float* Q  = (const float*)d_in[0];
    const float* K  = (const float*)d_in[1];
    const int*   nb = (const int*)d_in[2];
    const float* Wq = (const float*)d_in[3];
    const float* bq = (const float*)d_in[4];
    const float* Wk = (const float*)d_in[5];
    const float* bk = (const float*)d_in[6];
    const float* Wv = (const float*)d_in[7];
    const float* bv = (const float*)d_in[8];
    const float* Wo = (const float*)d_in[9];
    const float* bo = (const float*)d_in[10];
    float* out = (float*)d_out;

    float* Qh = 0;
    float* Kh = 0;
    float* Vh = 0;
    float* AV = 0;
    __nv_bfloat16* Wth = 0;
    __nv_bfloat16* Wtl = 0;
    cudaGetSymbolAddress((void**)&Qh, g_Qh);
    cudaGetSymbolAddress((void**)&Kh, g_Kh);
    cudaGetSymbolAddress((void**)&Vh, g_Vh);
    cudaGetSymbolAddress((void**)&AV, g_AV);
    cudaGetSymbolAddress((void**)&Wth, g_Wth);
    cudaGetSymbolAddress((void**)&Wtl, g_Wtl);

    // weight transpose + bf16 split (mat order: 0=Wq, 1=Wk, 2=Wv, 3=Wo)
    dim3 pgrid(256, 4);
    prep_w_kernel<<<pgrid, 256>>>(Wq, Wk, Wv, Wo);

    dim3 ggrid(2, 128);
    gemm_tc_kernel<<<ggrid, 256>>>(K, Wth + 65536, Wtl + 65536, bk, Kh);
    gemm_tc_kernel<<<ggrid, 256>>>(K, Wth + 2 * 65536, Wtl + 2 * 65536, bv, Vh);
    gemm_tc_kernel<<<ggrid, 256>>>(Q, Wth, Wtl, bq, Qh);

    knn_attn_kernel<<<16384, 256>>>(nb);

    gemm_tc_kernel<<<ggrid, 256>>>(AV, Wth + 3 * 65536, Wtl + 3 * 65536, bo, out);
}